// round 3
// baseline (speedup 1.0000x reference)
#include <cuda_runtime.h>
#include <math.h>

#define BB 256
#define TT 512
#define II 128
#define HH 256
#define H2 512
#define H3 768
#define GRID 148
#define NTHR 256
#define BK 32

enum { ACT_NONE = 0, ACT_RELU = 1, ACT_TANH = 2 };

// ---------------- persistent device scratch (no allocations) ----------------
__device__ float g_com[BB][H2];   // [c | c_in_t] input to W1
__device__ float g_a1[BB][H2];
__device__ float g_a2[BB][H2];
__device__ float g_a3[BB][H2];
__device__ float g_gi[BB][H3];    // c @ Wih^T + bih
__device__ float g_gh[BB][H3];    // h @ Whh^T + bhh
__device__ float g_c[BB][HH];
__device__ float g_h[BB][HH];
__device__ float g_n[BB];

__device__ unsigned g_bar_count;
__device__ volatile unsigned g_bar_gen;

// Software grid barrier. Safe: grid = 148 CTAs = #SMs, 1 CTA/SM, all wave-1 resident.
__device__ __forceinline__ void grid_sync() {
    __syncthreads();
    if (threadIdx.x == 0) {
        unsigned gen = g_bar_gen;
        __threadfence();                       // release: prior writes visible
        if (atomicAdd(&g_bar_count, 1u) == GRID - 1) {
            g_bar_count = 0;
            __threadfence();
            g_bar_gen = gen + 1;               // release all spinners
        } else {
            while (g_bar_gen == gen) __nanosleep(64);
        }
        __threadfence();                       // acquire
    }
    __syncthreads();
}

__device__ __forceinline__ float sigf(float x) { return 1.f / (1.f + expf(-x)); }

// -------------------------------------------------------------------------
// One 32xBN output tile of C = act(A @ W^T + bias).
// A: [M, lda] row-major. W: [N, ldw] row-major. 256 threads, TM=2, TN=BN/16.
// smem: As[BK][32+2] + Ws[BK][BN+4]
// -------------------------------------------------------------------------
template<int BN, int ACT>
__device__ void gemm_job(const float* __restrict__ A, int lda,
                         const float* __restrict__ W, int ldw,
                         const float* __restrict__ bias,
                         float* __restrict__ C, int ldc, int K,
                         int rowBase, int colBase, float* smem)
{
    constexpr int BM = 32;
    constexpr int TN = BN / 16;
    constexpr int ASP = BM + 2;
    constexpr int WSP = BN + 4;
    float* As = smem;
    float* Ws = smem + BK * ASP;

    const int tid = threadIdx.x;
    const int tx = tid & 15;       // column group
    const int ty = tid >> 4;       // row group (0..15)

    float acc[2][TN];
#pragma unroll
    for (int i = 0; i < 2; i++)
#pragma unroll
        for (int j = 0; j < TN; j++) acc[i][j] = 0.f;

    for (int k0 = 0; k0 < K; k0 += BK) {
        // load A tile: BM*BK/4 = 256 float4 -> 1 per thread
        {
            int r = tid >> 3, kq = tid & 7;
            float4 v = *(const float4*)(A + (size_t)(rowBase + r) * lda + k0 + kq * 4);
            As[(kq * 4 + 0) * ASP + r] = v.x;
            As[(kq * 4 + 1) * ASP + r] = v.y;
            As[(kq * 4 + 2) * ASP + r] = v.z;
            As[(kq * 4 + 3) * ASP + r] = v.w;
        }
        // load W tile: BN*BK/4 float4 -> BN/32 per thread
#pragma unroll
        for (int it = 0; it < BN / 32; it++) {
            int i = tid + it * 256;
            int r = i >> 3, kq = i & 7;
            float4 v = *(const float4*)(W + (size_t)(colBase + r) * ldw + k0 + kq * 4);
            Ws[(kq * 4 + 0) * WSP + r] = v.x;
            Ws[(kq * 4 + 1) * WSP + r] = v.y;
            Ws[(kq * 4 + 2) * WSP + r] = v.z;
            Ws[(kq * 4 + 3) * WSP + r] = v.w;
        }
        __syncthreads();
#pragma unroll
        for (int kk = 0; kk < BK; kk++) {
            float2 a = *(const float2*)&As[kk * ASP + ty * 2];
            if (TN == 4) {
                float4 w = *(const float4*)&Ws[kk * WSP + tx * 4];
                acc[0][0] = fmaf(a.x, w.x, acc[0][0]);
                acc[0][1] = fmaf(a.x, w.y, acc[0][1]);
                acc[0][2] = fmaf(a.x, w.z, acc[0][2]);
                acc[0][3] = fmaf(a.x, w.w, acc[0][3]);
                acc[1][0] = fmaf(a.y, w.x, acc[1][0]);
                acc[1][1] = fmaf(a.y, w.y, acc[1][1]);
                acc[1][2] = fmaf(a.y, w.z, acc[1][2]);
                acc[1][3] = fmaf(a.y, w.w, acc[1][3]);
            } else {
                float2 w = *(const float2*)&Ws[kk * WSP + tx * 2];
                acc[0][0] = fmaf(a.x, w.x, acc[0][0]);
                acc[0][1] = fmaf(a.x, w.y, acc[0][1]);
                acc[1][0] = fmaf(a.y, w.x, acc[1][0]);
                acc[1][1] = fmaf(a.y, w.y, acc[1][1]);
            }
        }
        __syncthreads();
    }
#pragma unroll
    for (int i = 0; i < 2; i++) {
        int row = rowBase + ty * 2 + i;
#pragma unroll
        for (int j = 0; j < TN; j++) {
            int col = colBase + tx * TN + j;
            float v = acc[i][j] + bias[col];
            if (ACT == ACT_RELU) v = fmaxf(v, 0.f);
            if (ACT == ACT_TANH) v = tanhf(v);
            C[(size_t)row * ldc + col] = v;
        }
    }
}

// ---------------- per-batch update (one b per call, 256 threads) ----------------
__device__ void update_batch(int b, int t, const float* __restrict__ W4,
                             const float* __restrict__ b4,
                             const float* __restrict__ noise,
                             const float* __restrict__ outC,
                             float* __restrict__ outH, float* smem)
{
    const int tid = threadIdx.x;
    float* sred = smem;            // 8 floats + 2 broadcast slots
    __syncthreads();

    // logit = a3[b,:] . W4 + b4  (512-wide dot)
    float part = g_a3[b][tid] * W4[tid] + g_a3[b][tid + 256] * W4[tid + 256];
#pragma unroll
    for (int s = 16; s > 0; s >>= 1) part += __shfl_down_sync(0xffffffffu, part, s);
    if ((tid & 31) == 0) sred[tid >> 5] = part;
    __syncthreads();
    if (tid == 0) {
        float logit = b4[0];
#pragma unroll
        for (int w = 0; w < 8; w++) logit += sred[w];
        float u = noise[(size_t)t * BB + b];
        float logistic = logf(u) - log1pf(-u);
        float a = sigf((logit + logistic) * 10.f);   // / TEMP(0.1)
        float nold = g_n[b];
        sred[8] = a;
        sred[9] = nold;
        g_n[b] = nold * (1.f - a) + 1.f;
    }
    __syncthreads();

    float alpha = sred[8], nold = sred[9];
    float c = g_c[b][tid], h = g_h[b][tid];
    float cin = outC[(size_t)b * TT * HH + (size_t)t * HH + tid];

    float r  = sigf(g_gi[b][tid] + g_gh[b][tid]);
    float z  = sigf(g_gi[b][HH + tid] + g_gh[b][HH + tid]);
    float ng = tanhf(g_gi[b][2 * HH + tid] + r * g_gh[b][2 * HH + tid]);
    float hcand = (1.f - z) * ng + z * h;

    float hnew = h * (1.f - alpha) + alpha * hcand;
    float nnew = nold * (1.f - alpha) + 1.f;
    float cnew = (c * nold * (1.f - alpha) + cin) / nnew;

    g_c[b][tid] = cnew;
    g_h[b][tid] = hnew;
    outH[(size_t)b * TT * HH + (size_t)t * HH + tid] = hnew;

    // pre-build next step's concat input [c_new | c_in(t+1)]
    g_com[b][tid] = cnew;
    if (t + 1 < TT)
        g_com[b][HH + tid] = outC[(size_t)b * TT * HH + (size_t)(t + 1) * HH + tid];
    __syncthreads();
}

// =========================== persistent megakernel ===========================
__global__ void __launch_bounds__(NTHR)
rnn_persistent(const float* __restrict__ input, const float* __restrict__ noise,
               const float* __restrict__ Wcin, const float* __restrict__ bcin,
               const float* __restrict__ W1, const float* __restrict__ b1,
               const float* __restrict__ W2, const float* __restrict__ b2,
               const float* __restrict__ W3, const float* __restrict__ b3,
               const float* __restrict__ W4, const float* __restrict__ b4,
               const float* __restrict__ Wih, const float* __restrict__ Whh,
               const float* __restrict__ bih, const float* __restrict__ bhh,
               float* __restrict__ outC, float* __restrict__ outH,
               float* __restrict__ outF)
{
    __shared__ float smem[BK * (32 + 2) + BK * (64 + 4)];   // 13056 B
    const int bid = blockIdx.x;
    const int tid = threadIdx.x;

    // -------- prologue: c_in = tanh(x @ Wcin^T) for all (b,t) -> c_concat --------
    // out row = b*T + t ; 32x64 tiles: (B*T/32) * (H/64) = 4096*4 = 16384 jobs
    for (int j = bid; j < 16384; j += GRID) {
        int rt = j >> 2, ct = j & 3;
        gemm_job<64, ACT_TANH>(input, II, Wcin, II, bcin, outC, HH, II,
                               rt * 32, ct * 64, smem);
    }
    grid_sync();

    // -------- init state --------
    for (int b = bid; b < BB; b += GRID) {
        g_c[b][tid] = 0.f;
        g_h[b][tid] = 0.f;
        g_com[b][tid] = 0.f;                                  // c0 = 0
        g_com[b][HH + tid] = outC[(size_t)b * TT * HH + tid]; // c_in at t=0
        if (tid == 0) g_n[b] = 0.f;
    }
    grid_sync();

    // -------- recurrent loop --------
    for (int t = 0; t < TT; t++) {
        // phase A: a1 (128 jobs 32x32 K=512) + gi (96 jobs 32x64 K=256) + gh (96)
        for (int j = bid; j < 320; j += GRID) {
            if (j < 128) {
                gemm_job<32, ACT_RELU>(&g_com[0][0], H2, W1, H2, b1,
                                       &g_a1[0][0], H2, H2,
                                       (j >> 4) * 32, (j & 15) * 32, smem);
            } else if (j < 224) {
                int q = j - 128;
                gemm_job<64, ACT_NONE>(&g_c[0][0], HH, Wih, HH, bih,
                                       &g_gi[0][0], H3, HH,
                                       (q / 12) * 32, (q % 12) * 64, smem);
            } else {
                int q = j - 224;
                gemm_job<64, ACT_NONE>(&g_h[0][0], HH, Whh, HH, bhh,
                                       &g_gh[0][0], H3, HH,
                                       (q / 12) * 32, (q % 12) * 64, smem);
            }
        }
        grid_sync();

        // phase B: a2 = relu(a1 @ W2^T)
        for (int j = bid; j < 128; j += GRID)
            gemm_job<32, ACT_RELU>(&g_a1[0][0], H2, W2, H2, b2,
                                   &g_a2[0][0], H2, H2,
                                   (j >> 4) * 32, (j & 15) * 32, smem);
        grid_sync();

        // phase C: a3 = relu(a2 @ W3^T)
        for (int j = bid; j < 128; j += GRID)
            gemm_job<32, ACT_RELU>(&g_a2[0][0], H2, W3, H2, b3,
                                   &g_a3[0][0], H2, H2,
                                   (j >> 4) * 32, (j & 15) * 32, smem);
        grid_sync();

        // phase U: alpha + GRU combine + state update
        for (int b = bid; b < BB; b += GRID)
            update_batch(b, t, W4, b4, noise, outC, outH, smem);
        grid_sync();
    }

    // -------- epilogue: h_final = gru_cell(c_T, h_T) --------
    for (int j = bid; j < 192; j += GRID) {
        if (j < 96) {
            gemm_job<64, ACT_NONE>(&g_c[0][0], HH, Wih, HH, bih,
                                   &g_gi[0][0], H3, HH,
                                   (j / 12) * 32, (j % 12) * 64, smem);
        } else {
            int q = j - 96;
            gemm_job<64, ACT_NONE>(&g_h[0][0], HH, Whh, HH, bhh,
                                   &g_gh[0][0], H3, HH,
                                   (q / 12) * 32, (q % 12) * 64, smem);
        }
    }
    grid_sync();
    for (int b = bid; b < BB; b += GRID) {
        float h = g_h[b][tid];
        float r  = sigf(g_gi[b][tid] + g_gh[b][tid]);
        float z  = sigf(g_gi[b][HH + tid] + g_gh[b][HH + tid]);
        float ng = tanhf(g_gi[b][2 * HH + tid] + r * g_gh[b][2 * HH + tid]);
        outF[(size_t)b * HH + tid] = (1.f - z) * ng + z * h;
    }
}

extern "C" void kernel_launch(void* const* d_in, const int* in_sizes, int n_in,
                              void* d_out, int out_size)
{
    const float* input = (const float*)d_in[0];
    const float* noise = (const float*)d_in[1];
    const float* Wcin  = (const float*)d_in[2];
    const float* bcin  = (const float*)d_in[3];
    const float* W1    = (const float*)d_in[4];
    const float* b1    = (const float*)d_in[5];
    const float* W2    = (const float*)d_in[6];
    const float* b2    = (const float*)d_in[7];
    const float* W3    = (const float*)d_in[8];
    const float* b3    = (const float*)d_in[9];
    const float* W4    = (const float*)d_in[10];
    const float* b4    = (const float*)d_in[11];
    const float* Wih   = (const float*)d_in[12];
    const float* Whh   = (const float*)d_in[13];
    const float* bih   = (const float*)d_in[14];
    const float* bhh   = (const float*)d_in[15];

    float* outC = (float*)d_out;                   // c_concat [B,T,H]
    float* outH = outC + (size_t)BB * TT * HH;     // h_concat [B,T,H]
    float* outF = outH + (size_t)BB * TT * HH;     // h_final  [B,H]

    rnn_persistent<<<GRID, NTHR>>>(input, noise, Wcin, bcin, W1, b1, W2, b2,
                                   W3, b3, W4, b4, Wih, Whh, bih, bhh,
                                   outC, outH, outF);
}

// round 4
// speedup vs baseline: 1.0423x; 1.0423x over previous
#include <cuda_runtime.h>
#include <math.h>

#define BB 256
#define TT 512
#define II 128
#define HH 256
#define H2 512
#define H3 768
#define GRID 148
#define NTHR 256
#define BK 32

enum { ACT_NONE = 0, ACT_RELU = 1, ACT_TANH = 2 };

// ---------------- persistent device scratch (no allocations) ----------------
__device__ float g_com[BB][H2];   // [c | c_in_t] input to W1
__device__ float g_a1[BB][H2];
__device__ float g_a2[BB][H2];
__device__ float g_a3[BB][H2];
__device__ float g_gi[BB][H3];    // c @ Wih^T + bih
__device__ float g_gh[BB][H3];    // h @ Whh^T + bhh
__device__ float g_c[BB][HH];
__device__ float g_h[BB][HH];
__device__ float g_n[BB];

__device__ unsigned g_bar_count;
__device__ volatile unsigned g_bar_gen;

// Software grid barrier. Safe: grid = 148 CTAs = #SMs, 1 CTA/SM, all wave-1 resident.
__device__ __forceinline__ void grid_sync() {
    __syncthreads();
    if (threadIdx.x == 0) {
        unsigned gen = g_bar_gen;
        __threadfence();                       // release: prior writes visible
        if (atomicAdd(&g_bar_count, 1u) == GRID - 1) {
            g_bar_count = 0;
            __threadfence();
            g_bar_gen = gen + 1;               // release all spinners
        } else {
            while (g_bar_gen == gen) __nanosleep(64);
        }
        __threadfence();                       // acquire
    }
    __syncthreads();
}

__device__ __forceinline__ float sigf(float x) { return 1.f / (1.f + expf(-x)); }

// -------------------------------------------------------------------------
// One 32xBN output tile of C = act(A @ W^T + bias).
// A: [M, lda] row-major. W: [N, ldw] row-major. 256 threads, TM=2, TN=BN/16.
// smem: As[BK][32+2] + Ws[BK][BN+4]
// -------------------------------------------------------------------------
template<int BN, int ACT>
__device__ void gemm_job(const float* __restrict__ A, int lda,
                         const float* __restrict__ W, int ldw,
                         const float* __restrict__ bias,
                         float* __restrict__ C, int ldc, int K,
                         int rowBase, int colBase, float* smem)
{
    constexpr int BM = 32;
    constexpr int TN = BN / 16;
    constexpr int ASP = BM + 2;
    constexpr int WSP = BN + 4;
    float* As = smem;
    float* Ws = smem + BK * ASP;

    const int tid = threadIdx.x;
    const int tx = tid & 15;       // column group
    const int ty = tid >> 4;       // row group (0..15)

    float acc[2][TN];
#pragma unroll
    for (int i = 0; i < 2; i++)
#pragma unroll
        for (int j = 0; j < TN; j++) acc[i][j] = 0.f;

    for (int k0 = 0; k0 < K; k0 += BK) {
        // load A tile: BM*BK/4 = 256 float4 -> 1 per thread
        {
            int r = tid >> 3, kq = tid & 7;
            float4 v = *(const float4*)(A + (size_t)(rowBase + r) * lda + k0 + kq * 4);
            As[(kq * 4 + 0) * ASP + r] = v.x;
            As[(kq * 4 + 1) * ASP + r] = v.y;
            As[(kq * 4 + 2) * ASP + r] = v.z;
            As[(kq * 4 + 3) * ASP + r] = v.w;
        }
        // load W tile: BN*BK/4 float4 -> BN/32 per thread
#pragma unroll
        for (int it = 0; it < BN / 32; it++) {
            int i = tid + it * 256;
            int r = i >> 3, kq = i & 7;
            float4 v = *(const float4*)(W + (size_t)(colBase + r) * ldw + k0 + kq * 4);
            Ws[(kq * 4 + 0) * WSP + r] = v.x;
            Ws[(kq * 4 + 1) * WSP + r] = v.y;
            Ws[(kq * 4 + 2) * WSP + r] = v.z;
            Ws[(kq * 4 + 3) * WSP + r] = v.w;
        }
        __syncthreads();
#pragma unroll
        for (int kk = 0; kk < BK; kk++) {
            float2 a = *(const float2*)&As[kk * ASP + ty * 2];
            if (TN == 4) {
                float4 w = *(const float4*)&Ws[kk * WSP + tx * 4];
                acc[0][0] = fmaf(a.x, w.x, acc[0][0]);
                acc[0][1] = fmaf(a.x, w.y, acc[0][1]);
                acc[0][2] = fmaf(a.x, w.z, acc[0][2]);
                acc[0][3] = fmaf(a.x, w.w, acc[0][3]);
                acc[1][0] = fmaf(a.y, w.x, acc[1][0]);
                acc[1][1] = fmaf(a.y, w.y, acc[1][1]);
                acc[1][2] = fmaf(a.y, w.z, acc[1][2]);
                acc[1][3] = fmaf(a.y, w.w, acc[1][3]);
            } else {
                float2 w = *(const float2*)&Ws[kk * WSP + tx * 2];
                acc[0][0] = fmaf(a.x, w.x, acc[0][0]);
                acc[0][1] = fmaf(a.x, w.y, acc[0][1]);
                acc[1][0] = fmaf(a.y, w.x, acc[1][0]);
                acc[1][1] = fmaf(a.y, w.y, acc[1][1]);
            }
        }
        __syncthreads();
    }
#pragma unroll
    for (int i = 0; i < 2; i++) {
        int row = rowBase + ty * 2 + i;
#pragma unroll
        for (int j = 0; j < TN; j++) {
            int col = colBase + tx * TN + j;
            float v = acc[i][j] + bias[col];
            if (ACT == ACT_RELU) v = fmaxf(v, 0.f);
            if (ACT == ACT_TANH) v = tanhf(v);
            C[(size_t)row * ldc + col] = v;
        }
    }
}

// ---------------- per-batch update (one b per call, 256 threads) ----------------
__device__ void update_batch(int b, int t, const float* __restrict__ W4,
                             const float* __restrict__ b4,
                             const float* __restrict__ noise,
                             const float* __restrict__ outC,
                             float* __restrict__ outH, float* smem)
{
    const int tid = threadIdx.x;
    float* sred = smem;            // 8 floats + 2 broadcast slots
    __syncthreads();

    // logit = a3[b,:] . W4 + b4  (512-wide dot)
    float part = g_a3[b][tid] * W4[tid] + g_a3[b][tid + 256] * W4[tid + 256];
#pragma unroll
    for (int s = 16; s > 0; s >>= 1) part += __shfl_down_sync(0xffffffffu, part, s);
    if ((tid & 31) == 0) sred[tid >> 5] = part;
    __syncthreads();
    if (tid == 0) {
        float logit = b4[0];
#pragma unroll
        for (int w = 0; w < 8; w++) logit += sred[w];
        float u = noise[(size_t)t * BB + b];
        float logistic = logf(u) - log1pf(-u);
        float a = sigf((logit + logistic) * 10.f);   // / TEMP(0.1)
        float nold = g_n[b];
        sred[8] = a;
        sred[9] = nold;
        g_n[b] = nold * (1.f - a) + 1.f;
    }
    __syncthreads();

    float alpha = sred[8], nold = sred[9];
    float c = g_c[b][tid], h = g_h[b][tid];
    float cin = outC[(size_t)b * TT * HH + (size_t)t * HH + tid];

    float r  = sigf(g_gi[b][tid] + g_gh[b][tid]);
    float z  = sigf(g_gi[b][HH + tid] + g_gh[b][HH + tid]);
    float ng = tanhf(g_gi[b][2 * HH + tid] + r * g_gh[b][2 * HH + tid]);
    float hcand = (1.f - z) * ng + z * h;

    float hnew = h * (1.f - alpha) + alpha * hcand;
    float nnew = nold * (1.f - alpha) + 1.f;
    float cnew = (c * nold * (1.f - alpha) + cin) / nnew;

    g_c[b][tid] = cnew;
    g_h[b][tid] = hnew;
    outH[(size_t)b * TT * HH + (size_t)t * HH + tid] = hnew;

    // pre-build next step's concat input [c_new | c_in(t+1)]
    g_com[b][tid] = cnew;
    if (t + 1 < TT)
        g_com[b][HH + tid] = outC[(size_t)b * TT * HH + (size_t)(t + 1) * HH + tid];
    __syncthreads();
}

// =========================== persistent megakernel ===========================
__global__ void __launch_bounds__(NTHR)
rnn_persistent(const float* __restrict__ input, const float* __restrict__ noise,
               const float* __restrict__ Wcin, const float* __restrict__ bcin,
               const float* __restrict__ W1, const float* __restrict__ b1,
               const float* __restrict__ W2, const float* __restrict__ b2,
               const float* __restrict__ W3, const float* __restrict__ b3,
               const float* __restrict__ W4, const float* __restrict__ b4,
               const float* __restrict__ Wih, const float* __restrict__ Whh,
               const float* __restrict__ bih, const float* __restrict__ bhh,
               float* __restrict__ outC, float* __restrict__ outH,
               float* __restrict__ outF)
{
    __shared__ float smem[BK * (32 + 2) + BK * (64 + 4)];   // 13056 B
    const int bid = blockIdx.x;
    const int tid = threadIdx.x;

    // -------- prologue: c_in = tanh(x @ Wcin^T) for all (b,t) -> c_concat --------
    // out row = b*T + t ; 32x64 tiles: (B*T/32) * (H/64) = 4096*4 = 16384 jobs
    for (int j = bid; j < 16384; j += GRID) {
        int rt = j >> 2, ct = j & 3;
        gemm_job<64, ACT_TANH>(input, II, Wcin, II, bcin, outC, HH, II,
                               rt * 32, ct * 64, smem);
    }
    grid_sync();

    // -------- init state --------
    for (int b = bid; b < BB; b += GRID) {
        g_c[b][tid] = 0.f;
        g_h[b][tid] = 0.f;
        g_com[b][tid] = 0.f;                                  // c0 = 0
        g_com[b][HH + tid] = outC[(size_t)b * TT * HH + tid]; // c_in at t=0
        if (tid == 0) g_n[b] = 0.f;
    }
    grid_sync();

    // -------- recurrent loop --------
    for (int t = 0; t < TT; t++) {
        // phase A: a1 (128 jobs 32x32 K=512) + gi (96 jobs 32x64 K=256) + gh (96)
        for (int j = bid; j < 320; j += GRID) {
            if (j < 128) {
                gemm_job<32, ACT_RELU>(&g_com[0][0], H2, W1, H2, b1,
                                       &g_a1[0][0], H2, H2,
                                       (j >> 4) * 32, (j & 15) * 32, smem);
            } else if (j < 224) {
                int q = j - 128;
                gemm_job<64, ACT_NONE>(&g_c[0][0], HH, Wih, HH, bih,
                                       &g_gi[0][0], H3, HH,
                                       (q / 12) * 32, (q % 12) * 64, smem);
            } else {
                int q = j - 224;
                gemm_job<64, ACT_NONE>(&g_h[0][0], HH, Whh, HH, bhh,
                                       &g_gh[0][0], H3, HH,
                                       (q / 12) * 32, (q % 12) * 64, smem);
            }
        }
        grid_sync();

        // phase B: a2 = relu(a1 @ W2^T)
        for (int j = bid; j < 128; j += GRID)
            gemm_job<32, ACT_RELU>(&g_a1[0][0], H2, W2, H2, b2,
                                   &g_a2[0][0], H2, H2,
                                   (j >> 4) * 32, (j & 15) * 32, smem);
        grid_sync();

        // phase C: a3 = relu(a2 @ W3^T)
        for (int j = bid; j < 128; j += GRID)
            gemm_job<32, ACT_RELU>(&g_a2[0][0], H2, W3, H2, b3,
                                   &g_a3[0][0], H2, H2,
                                   (j >> 4) * 32, (j & 15) * 32, smem);
        grid_sync();

        // phase U: alpha + GRU combine + state update
        for (int b = bid; b < BB; b += GRID)
            update_batch(b, t, W4, b4, noise, outC, outH, smem);
        grid_sync();
    }

    // -------- epilogue: h_final = gru_cell(c_T, h_T) --------
    for (int j = bid; j < 192; j += GRID) {
        if (j < 96) {
            gemm_job<64, ACT_NONE>(&g_c[0][0], HH, Wih, HH, bih,
                                   &g_gi[0][0], H3, HH,
                                   (j / 12) * 32, (j % 12) * 64, smem);
        } else {
            int q = j - 96;
            gemm_job<64, ACT_NONE>(&g_h[0][0], HH, Whh, HH, bhh,
                                   &g_gh[0][0], H3, HH,
                                   (q / 12) * 32, (q % 12) * 64, smem);
        }
    }
    grid_sync();
    for (int b = bid; b < BB; b += GRID) {
        float h = g_h[b][tid];
        float r  = sigf(g_gi[b][tid] + g_gh[b][tid]);
        float z  = sigf(g_gi[b][HH + tid] + g_gh[b][HH + tid]);
        float ng = tanhf(g_gi[b][2 * HH + tid] + r * g_gh[b][2 * HH + tid]);
        outF[(size_t)b * HH + tid] = (1.f - z) * ng + z * h;
    }
}

extern "C" void kernel_launch(void* const* d_in, const int* in_sizes, int n_in,
                              void* d_out, int out_size)
{
    const float* input = (const float*)d_in[0];
    const float* noise = (const float*)d_in[1];
    const float* Wcin  = (const float*)d_in[2];
    const float* bcin  = (const float*)d_in[3];
    const float* W1    = (const float*)d_in[4];
    const float* b1    = (const float*)d_in[5];
    const float* W2    = (const float*)d_in[6];
    const float* b2    = (const float*)d_in[7];
    const float* W3    = (const float*)d_in[8];
    const float* b3    = (const float*)d_in[9];
    const float* W4    = (const float*)d_in[10];
    const float* b4    = (const float*)d_in[11];
    const float* Wih   = (const float*)d_in[12];
    const float* Whh   = (const float*)d_in[13];
    const float* bih   = (const float*)d_in[14];
    const float* bhh   = (const float*)d_in[15];

    float* outC = (float*)d_out;                   // c_concat [B,T,H]
    float* outH = outC + (size_t)BB * TT * HH;     // h_concat [B,T,H]
    float* outF = outH + (size_t)BB * TT * HH;     // h_final  [B,H]

    rnn_persistent<<<GRID, NTHR>>>(input, noise, Wcin, bcin, W1, b1, W2, b2,
                                   W3, b3, W4, b4, Wih, Whh, bih, bhh,
                                   outC, outH, outF);
}

// round 5
// speedup vs baseline: 1.2617x; 1.2104x over previous
#include <cuda_runtime.h>
#include <math.h>

#define BB 256
#define TT 512
#define II 128
#define HH 256
#define H2 512
#define H3 768
#define SMS 148
#define GRID 296          // 2 CTAs per SM
#define NTHR 128

typedef unsigned long long ull;

// smem geometry (per buffer): A duplicated pairs [32k][33 ull], W [32k][36 f]
#define ASP2 33
#define WSP  36
#define SA_BUF (32 * ASP2)     // ull units
#define SW_BUF (32 * WSP)      // float units

enum { EPI_RAW = 0, EPI_BIAS = 1, EPI_TANH = 2 };

// ---------------- persistent device scratch (no allocations) ----------------
__device__ float g_com[BB][H2];        // [c | c_in_t]
__device__ float g_a1p[2][BB][H2];     // K-split partials of layer1
__device__ float g_a2p[2][BB][H2];
__device__ float g_a3p[2][BB][H2];
__device__ float g_gi[BB][H3];
__device__ float g_gh[BB][H3];
__device__ float g_c[BB][HH];
__device__ float g_h[BB][HH];
__device__ float g_n[BB];

__device__ unsigned g_bar_count;
__device__ volatile unsigned g_bar_gen;

__device__ __forceinline__ void grid_sync() {
    __syncthreads();
    if (threadIdx.x == 0) {
        unsigned gen = g_bar_gen;
        __threadfence();
        if (atomicAdd(&g_bar_count, 1u) == GRID - 1) {
            g_bar_count = 0;
            __threadfence();
            g_bar_gen = gen + 1;
        } else {
            while (g_bar_gen == gen) __nanosleep(32);
        }
        __threadfence();
    }
    __syncthreads();
}

__device__ __forceinline__ float sigf(float x) { return 1.f / (1.f + expf(-x)); }

// ---------------- packed f32x2 helpers ----------------
__device__ __forceinline__ ull pack2(float x, float y) {
    ull r; asm("mov.b64 %0,{%1,%2};" : "=l"(r) : "f"(x), "f"(y)); return r;
}
__device__ __forceinline__ void unpack2(ull v, float& x, float& y) {
    asm("mov.b64 {%0,%1},%2;" : "=f"(x), "=f"(y) : "l"(v));
}
__device__ __forceinline__ void fma2(ull& d, ull a, ull b) {
    asm("fma.rn.f32x2 %0, %1, %2, %0;" : "+l"(d) : "l"(a), "l"(b));
}

// -------------------------------------------------------------------------
// One 32x32 output tile of C = epi(A @ W^T), K multiple of 32, 128 threads.
// A: [*, lda] row-major (optionally combined: relu(A0+A1+Ab) elementwise),
// W: [N, ldw] row-major. Double-buffered smem; A stored duplicated for FFMA2.
// -------------------------------------------------------------------------
template<int EPI, bool COMBINE>
__device__ void gemm_job(const float* __restrict__ A0, const float* __restrict__ A1,
                         const float* __restrict__ Ab, int lda, int aoff,
                         const float* __restrict__ W, int ldw, int woff,
                         const float* __restrict__ bias,
                         float* __restrict__ C, int ldc,
                         int rowBase, int colBase, int K,
                         ull* __restrict__ sA, float* __restrict__ sW)
{
    const int tid = threadIdx.x;
    const int tx = tid & 7;        // col group (4 cols)
    const int ty = tid >> 3;       // row pair (0..15)
    const int kq = tid & 7;        // loader k-quad
    const int r0 = tid >> 3;       // loader row (and r0+16)

    ull c00 = 0, c01 = 0, c10 = 0, c11 = 0;
    float4 va0, va1, vw0, vw1;

    const int NT = K >> 5;

#define LOAD_TILE(kt)                                                          \
    {                                                                          \
        int gka = aoff + (kt) * 32 + kq * 4;                                   \
        va0 = *(const float4*)(A0 + (size_t)(rowBase + r0) * lda + gka);       \
        va1 = *(const float4*)(A0 + (size_t)(rowBase + r0 + 16) * lda + gka);  \
        if (COMBINE) {                                                         \
            float4 u0 = *(const float4*)(A1 + (size_t)(rowBase + r0) * lda + gka);      \
            float4 u1 = *(const float4*)(A1 + (size_t)(rowBase + r0 + 16) * lda + gka); \
            float4 bb = *(const float4*)(Ab + gka);                            \
            va0.x = fmaxf(va0.x + u0.x + bb.x, 0.f);                           \
            va0.y = fmaxf(va0.y + u0.y + bb.y, 0.f);                           \
            va0.z = fmaxf(va0.z + u0.z + bb.z, 0.f);                           \
            va0.w = fmaxf(va0.w + u0.w + bb.w, 0.f);                           \
            va1.x = fmaxf(va1.x + u1.x + bb.x, 0.f);                           \
            va1.y = fmaxf(va1.y + u1.y + bb.y, 0.f);                           \
            va1.z = fmaxf(va1.z + u1.z + bb.z, 0.f);                           \
            va1.w = fmaxf(va1.w + u1.w + bb.w, 0.f);                           \
        }                                                                      \
        int gkw = woff + (kt) * 32 + kq * 4;                                   \
        vw0 = *(const float4*)(W + (size_t)(colBase + r0) * ldw + gkw);        \
        vw1 = *(const float4*)(W + (size_t)(colBase + r0 + 16) * ldw + gkw);   \
    }

#define STORE_TILE(bi)                                                         \
    {                                                                          \
        ull*   As = sA + (bi) * SA_BUF;                                        \
        float* Ws = sW + (bi) * SW_BUF;                                        \
        As[(kq * 4 + 0) * ASP2 + r0]      = pack2(va0.x, va0.x);               \
        As[(kq * 4 + 1) * ASP2 + r0]      = pack2(va0.y, va0.y);               \
        As[(kq * 4 + 2) * ASP2 + r0]      = pack2(va0.z, va0.z);               \
        As[(kq * 4 + 3) * ASP2 + r0]      = pack2(va0.w, va0.w);               \
        As[(kq * 4 + 0) * ASP2 + r0 + 16] = pack2(va1.x, va1.x);               \
        As[(kq * 4 + 1) * ASP2 + r0 + 16] = pack2(va1.y, va1.y);               \
        As[(kq * 4 + 2) * ASP2 + r0 + 16] = pack2(va1.z, va1.z);               \
        As[(kq * 4 + 3) * ASP2 + r0 + 16] = pack2(va1.w, va1.w);               \
        Ws[(kq * 4 + 0) * WSP + r0]      = vw0.x;                              \
        Ws[(kq * 4 + 1) * WSP + r0]      = vw0.y;                              \
        Ws[(kq * 4 + 2) * WSP + r0]      = vw0.z;                              \
        Ws[(kq * 4 + 3) * WSP + r0]      = vw0.w;                              \
        Ws[(kq * 4 + 0) * WSP + r0 + 16] = vw1.x;                              \
        Ws[(kq * 4 + 1) * WSP + r0 + 16] = vw1.y;                              \
        Ws[(kq * 4 + 2) * WSP + r0 + 16] = vw1.z;                              \
        Ws[(kq * 4 + 3) * WSP + r0 + 16] = vw1.w;                              \
    }

    LOAD_TILE(0);
    STORE_TILE(0);
    __syncthreads();

    for (int kt = 0; kt < NT; kt++) {
        if (kt + 1 < NT) LOAD_TILE(kt + 1);
        {
            const ull*   As = sA + (kt & 1) * SA_BUF;
            const float* Ws = sW + (kt & 1) * SW_BUF;
#pragma unroll
            for (int kk = 0; kk < 32; kk++) {
                ull a0  = As[kk * ASP2 + 2 * ty];
                ull a1  = As[kk * ASP2 + 2 * ty + 1];
                ull w01 = *(const ull*)(Ws + kk * WSP + tx * 4);
                ull w23 = *(const ull*)(Ws + kk * WSP + tx * 4 + 2);
                fma2(c00, a0, w01);
                fma2(c01, a0, w23);
                fma2(c10, a1, w01);
                fma2(c11, a1, w23);
            }
        }
        if (kt + 1 < NT) STORE_TILE((kt + 1) & 1);
        __syncthreads();
    }
#undef LOAD_TILE
#undef STORE_TILE

    // epilogue
    int crow = rowBase + 2 * ty;
    int ccol = colBase + tx * 4;
    float4 o0, o1;
    unpack2(c00, o0.x, o0.y); unpack2(c01, o0.z, o0.w);
    unpack2(c10, o1.x, o1.y); unpack2(c11, o1.z, o1.w);
    if (EPI != EPI_RAW) {
        float4 bb = *(const float4*)(bias + ccol);
        o0.x += bb.x; o0.y += bb.y; o0.z += bb.z; o0.w += bb.w;
        o1.x += bb.x; o1.y += bb.y; o1.z += bb.z; o1.w += bb.w;
        if (EPI == EPI_TANH) {
            o0.x = tanhf(o0.x); o0.y = tanhf(o0.y); o0.z = tanhf(o0.z); o0.w = tanhf(o0.w);
            o1.x = tanhf(o1.x); o1.y = tanhf(o1.y); o1.z = tanhf(o1.z); o1.w = tanhf(o1.w);
        }
    }
    *(float4*)(C + (size_t)crow * ldc + ccol) = o0;
    *(float4*)(C + (size_t)(crow + 1) * ldc + ccol) = o1;
}

// ---------------- job dispatch ----------------
// phases 0(A),1(B),2(C): 384 jobs each; phase 3 (epilogue gi/gh): 384 jobs
struct WPtrs {
    const float *W1, *b1, *W2, *b2, *W3, *b3, *Wih, *Whh, *bih, *bhh;
};

__device__ void exec_job(int ph, int j, const WPtrs& w, ull* sA, float* sW)
{
    if (ph < 3 && j < 256) {
        int rt = j >> 5, rem = j & 31;
        int p = rem >> 4, ct = rem & 15;
        int rb = rt * 32, cb = ct * 32, ko = p * 256;
        if (ph == 0)
            gemm_job<EPI_RAW, false>(&g_com[0][0], 0, 0, H2, ko,
                                     w.W1, H2, ko, 0,
                                     &g_a1p[p][0][0], H2, rb, cb, 256, sA, sW);
        else if (ph == 1)
            gemm_job<EPI_RAW, true>(&g_a1p[0][0][0], &g_a1p[1][0][0], w.b1, H2, ko,
                                    w.W2, H2, ko, 0,
                                    &g_a2p[p][0][0], H2, rb, cb, 256, sA, sW);
        else
            gemm_job<EPI_RAW, true>(&g_a2p[0][0][0], &g_a2p[1][0][0], w.b2, H2, ko,
                                    w.W3, H2, ko, 0,
                                    &g_a3p[p][0][0], H2, rb, cb, 256, sA, sW);
    } else {
        int q; bool is_gi;
        if (ph == 0)      { q = j - 256;        is_gi = true;  }        // gi 0..127
        else if (ph == 1) { if (j < 320) { q = j - 256 + 128; is_gi = true; }   // gi 128..191
                            else         { q = j - 320;       is_gi = false; } } // gh 0..63
        else if (ph == 2) { q = j - 256 + 64;   is_gi = false; }        // gh 64..191
        else              { if (j < 192) { q = j; is_gi = true; }
                            else         { q = j - 192; is_gi = false; } }
        int rt = q / 24, ct = q % 24;
        if (is_gi)
            gemm_job<EPI_BIAS, false>(&g_c[0][0], 0, 0, HH, 0,
                                      w.Wih, HH, 0, w.bih,
                                      &g_gi[0][0], H3, rt * 32, ct * 32, 256, sA, sW);
        else
            gemm_job<EPI_BIAS, false>(&g_h[0][0], 0, 0, HH, 0,
                                      w.Whh, HH, 0, w.bhh,
                                      &g_gh[0][0], H3, rt * 32, ct * 32, 256, sA, sW);
    }
}

// per-SM balanced assignment of 384 jobs: SMs 0..87 -> 3 jobs, 88..147 -> 2
__device__ void run_phase(int ph, int s, int slot, const WPtrs& w, ull* sA, float* sW)
{
    int n    = (s < 88) ? 3 : 2;
    int base = (s < 88) ? 3 * s : 264 + 2 * (s - 88);
    if (!slot) {
        exec_job(ph, base, w, sA, sW);
        if (n == 3) exec_job(ph, base + 1, w, sA, sW);
    } else {
        exec_job(ph, base + n - 1, w, sA, sW);
    }
}

// =========================== persistent megakernel ===========================
__global__ void __launch_bounds__(NTHR)
rnn_persistent(const float* __restrict__ input, const float* __restrict__ noise,
               const float* __restrict__ Wcin, const float* __restrict__ bcin,
               const float* __restrict__ W1, const float* __restrict__ b1,
               const float* __restrict__ W2, const float* __restrict__ b2,
               const float* __restrict__ W3, const float* __restrict__ b3,
               const float* __restrict__ W4, const float* __restrict__ b4,
               const float* __restrict__ Wih, const float* __restrict__ Whh,
               const float* __restrict__ bih, const float* __restrict__ bhh,
               float* __restrict__ outC, float* __restrict__ outH,
               float* __restrict__ outF)
{
    __shared__ ull   sA[2 * SA_BUF];
    __shared__ float sW[2 * SW_BUF];
    __shared__ float su[8];

    const int bid = blockIdx.x;
    const int tid = threadIdx.x;
    const int s    = (bid < SMS) ? bid : bid - SMS;
    const int slot = (bid >= SMS);

    WPtrs w { W1, b1, W2, b2, W3, b3, Wih, Whh, bih, bhh };

    // -------- prologue: c_in = tanh(x @ Wcin^T) -> c_concat (row = b*T+t) --------
    for (int j = bid; j < 32768; j += GRID) {
        int rt = j >> 3, ct = j & 7;
        gemm_job<EPI_TANH, false>(input, 0, 0, II, 0, Wcin, II, 0, bcin,
                                  outC, HH, rt * 32, ct * 32, II, sA, sW);
    }
    grid_sync();

    // -------- init state --------
    if (bid < BB) {
        int b = bid;
        for (int j = tid; j < HH; j += NTHR) {
            g_c[b][j] = 0.f;
            g_h[b][j] = 0.f;
            g_com[b][j] = 0.f;
            g_com[b][HH + j] = outC[(size_t)b * TT * HH + j];
        }
        if (tid == 0) g_n[b] = 0.f;
    }
    grid_sync();

    // -------- recurrent loop --------
    for (int t = 0; t < TT; t++) {
        run_phase(0, s, slot, w, sA, sW);   // a1 partials + gi[0:128)
        grid_sync();
        run_phase(1, s, slot, w, sA, sW);   // a2 partials + gi[128:192) + gh[0:64)
        grid_sync();
        run_phase(2, s, slot, w, sA, sW);   // a3 partials + gh[64:192)
        grid_sync();

        // -------- phase U: alpha + GRU + state update --------
        if (bid < BB) {
            int b = bid;
            float part = 0.f;
            for (int k = tid; k < H2; k += NTHR) {
                float v = g_a3p[0][b][k] + g_a3p[1][b][k] + b3[k];
                v = fmaxf(v, 0.f);
                part += v * W4[k];
            }
#pragma unroll
            for (int sh = 16; sh > 0; sh >>= 1)
                part += __shfl_down_sync(0xffffffffu, part, sh);
            if ((tid & 31) == 0) su[tid >> 5] = part;
            __syncthreads();
            if (tid == 0) {
                float logit = b4[0] + su[0] + su[1] + su[2] + su[3];
                float u = noise[(size_t)t * BB + b];
                float logistic = logf(u) - log1pf(-u);
                float a = sigf((logit + logistic) * 10.f);   // / TEMP
                float nold = g_n[b];
                su[4] = a;
                su[5] = nold;
                g_n[b] = nold * (1.f - a) + 1.f;
            }
            __syncthreads();
            float alpha = su[4], nold = su[5];
            float nnew = nold * (1.f - alpha) + 1.f;
#pragma unroll
            for (int u2 = 0; u2 < 2; u2++) {
                int jj = tid + u2 * NTHR;
                float c = g_c[b][jj], h = g_h[b][jj];
                float cin = outC[(size_t)b * TT * HH + (size_t)t * HH + jj];
                float r  = sigf(g_gi[b][jj] + g_gh[b][jj]);
                float z  = sigf(g_gi[b][HH + jj] + g_gh[b][HH + jj]);
                float ng = tanhf(g_gi[b][2 * HH + jj] + r * g_gh[b][2 * HH + jj]);
                float hcand = (1.f - z) * ng + z * h;
                float hnew = h * (1.f - alpha) + alpha * hcand;
                float cnew = (c * nold * (1.f - alpha) + cin) / nnew;
                g_c[b][jj] = cnew;
                g_h[b][jj] = hnew;
                outH[(size_t)b * TT * HH + (size_t)t * HH + jj] = hnew;
                g_com[b][jj] = cnew;
                if (t + 1 < TT)
                    g_com[b][HH + jj] = outC[(size_t)b * TT * HH + (size_t)(t + 1) * HH + jj];
            }
        }
        grid_sync();
    }

    // -------- epilogue: h_final = gru_cell(c_T, h_T) --------
    run_phase(3, s, slot, w, sA, sW);       // gi + gh (384 jobs)
    grid_sync();
    if (bid < BB) {
        int b = bid;
#pragma unroll
        for (int u2 = 0; u2 < 2; u2++) {
            int jj = tid + u2 * NTHR;
            float h = g_h[b][jj];
            float r  = sigf(g_gi[b][jj] + g_gh[b][jj]);
            float z  = sigf(g_gi[b][HH + jj] + g_gh[b][HH + jj]);
            float ng = tanhf(g_gi[b][2 * HH + jj] + r * g_gh[b][2 * HH + jj]);
            outF[(size_t)b * HH + jj] = (1.f - z) * ng + z * h;
        }
    }
}

extern "C" void kernel_launch(void* const* d_in, const int* in_sizes, int n_in,
                              void* d_out, int out_size)
{
    const float* input = (const float*)d_in[0];
    const float* noise = (const float*)d_in[1];
    const float* Wcin  = (const float*)d_in[2];
    const float* bcin  = (const float*)d_in[3];
    const float* W1    = (const float*)d_in[4];
    const float* b1    = (const float*)d_in[5];
    const float* W2    = (const float*)d_in[6];
    const float* b2    = (const float*)d_in[7];
    const float* W3    = (const float*)d_in[8];
    const float* b3    = (const float*)d_in[9];
    const float* W4    = (const float*)d_in[10];
    const float* b4    = (const float*)d_in[11];
    const float* Wih   = (const float*)d_in[12];
    const float* Whh   = (const float*)d_in[13];
    const float* bih   = (const float*)d_in[14];
    const float* bhh   = (const float*)d_in[15];

    float* outC = (float*)d_out;                   // c_concat [B,T,H]
    float* outH = outC + (size_t)BB * TT * HH;     // h_concat [B,T,H]
    float* outF = outH + (size_t)BB * TT * HH;     // h_final  [B,H]

    rnn_persistent<<<GRID, NTHR>>>(input, noise, Wcin, bcin, W1, b1, W2, b2,
                                   W3, b3, W4, b4, Wih, Whh, bih, bhh,
                                   outC, outH, outF);
}

// round 6
// speedup vs baseline: 1.6112x; 1.2771x over previous
#include <cuda_runtime.h>
#include <math.h>

#define BB 256
#define TT 512
#define II 128
#define HH 256
#define H2 512
#define H3 768
#define SMS 148
#define GRID 296
#define NTHR 128
#define GSTRIDE (GRID * NTHR)

typedef unsigned long long ull;

#define ASP 36            // As row pitch (floats)
#define WSP 68            // Ws row pitch (floats)
#define SA_BUF (32 * ASP)
#define SW_BUF (32 * WSP)

enum { EPI_RAW = 0, EPI_BIAS = 1, EPI_TANH = 2 };

// ---------------- persistent device scratch (no allocations) ----------------
__device__ float g_W1t[H2 * H2];     // transposed weights: Wt[k][n] = W[n][k]
__device__ float g_W2t[H2 * H2];
__device__ float g_W3t[H2 * H2];
__device__ float g_WihT[HH * H3];
__device__ float g_WhhT[HH * H3];
__device__ float g_WcinT[II * HH];

__device__ float g_com[BB][H2];      // [c | c_in_t]
__device__ float g_a1p[2][BB][H2];   // K-split partials
__device__ float g_a2p[2][BB][H2];
__device__ float g_a3p[2][BB][H2];
__device__ float g_gi[BB][H3];
__device__ float g_gh[BB][H3];
__device__ float g_c[BB][HH];
__device__ float g_h[BB][HH];
__device__ float g_n[BB];

__device__ unsigned g_bar_count;
__device__ volatile unsigned g_bar_gen;

__device__ __forceinline__ void grid_sync() {
    __syncthreads();
    if (threadIdx.x == 0) {
        unsigned gen = g_bar_gen;
        __threadfence();
        if (atomicAdd(&g_bar_count, 1u) == GRID - 1) {
            g_bar_count = 0;
            __threadfence();
            g_bar_gen = gen + 1;
        } else {
            while (g_bar_gen == gen) __nanosleep(32);
        }
        __threadfence();
    }
    __syncthreads();
}

__device__ __forceinline__ float sigf(float x) { return 1.f / (1.f + expf(-x)); }

// ---------------- packed f32x2 helpers ----------------
__device__ __forceinline__ ull pack2(float x, float y) {
    ull r; asm("mov.b64 %0,{%1,%2};" : "=l"(r) : "f"(x), "f"(y)); return r;
}
__device__ __forceinline__ void unpack2(ull v, float& x, float& y) {
    asm("mov.b64 {%0,%1},%2;" : "=f"(x), "=f"(y) : "l"(v));
}
__device__ __forceinline__ void fma2(ull& d, ull a, ull b) {
    asm("fma.rn.f32x2 %0, %1, %2, %0;" : "+l"(d) : "l"(a), "l"(b));
}

// -------------------------------------------------------------------------
// One 32x64 output tile of C = epi(A @ Wt), 128 threads, per-thread 2x8.
// A: [*, lda] row-major activations (optionally relu(A0+A1+Ab) on the fly).
// Wt: [K, ldw] row-major TRANSPOSED weights (k-major).
// Double-buffered smem, one __syncthreads per k-tile.
// -------------------------------------------------------------------------
template<int EPI, bool COMBINE>
__device__ __noinline__ void gemm32x64(
    const float* __restrict__ A0, const float* __restrict__ A1,
    const float* __restrict__ Ab, int lda, int koff,
    const float* __restrict__ Wt, int ldw,
    const float* __restrict__ bias,
    float* __restrict__ C, int ldc,
    int rowBase, int colBase, int nkt,
    float* __restrict__ As, float* __restrict__ Ws)
{
    const int tid  = threadIdx.x;
    const int tx4  = (tid & 7) * 4;        // col block offset
    const int ty2  = (tid >> 3) * 2;       // row pair
    const int arow = tid >> 3;             // A-stage row (and +16)
    const int akq  = tid & 7;              // A-stage k-quad
    const int wkk  = tid >> 4;             // W-stage kk (0..7, +8,+16,+24)
    const int wc4  = (tid & 15) * 4;       // W-stage col quad

    ull c00 = 0, c01 = 0, c02 = 0, c03 = 0;
    ull c10 = 0, c11 = 0, c12 = 0, c13 = 0;
    float4 va0, va1, vw0, vw1, vw2, vw3;

#define LOAD_T(kt)                                                              \
    {                                                                           \
        int kg = koff + (kt) * 32;                                              \
        const float* ap = A0 + (size_t)(rowBase + arow) * lda + kg + akq * 4;   \
        va0 = *(const float4*)ap;                                               \
        va1 = *(const float4*)(ap + 16 * (size_t)lda);                          \
        if (COMBINE) {                                                          \
            const float* a1p = A1 + (size_t)(rowBase + arow) * lda + kg + akq * 4; \
            float4 u0 = *(const float4*)a1p;                                    \
            float4 u1 = *(const float4*)(a1p + 16 * (size_t)lda);               \
            float4 bb = *(const float4*)(Ab + kg + akq * 4);                    \
            va0.x = fmaxf(va0.x + u0.x + bb.x, 0.f);                            \
            va0.y = fmaxf(va0.y + u0.y + bb.y, 0.f);                            \
            va0.z = fmaxf(va0.z + u0.z + bb.z, 0.f);                            \
            va0.w = fmaxf(va0.w + u0.w + bb.w, 0.f);                            \
            va1.x = fmaxf(va1.x + u1.x + bb.x, 0.f);                            \
            va1.y = fmaxf(va1.y + u1.y + bb.y, 0.f);                            \
            va1.z = fmaxf(va1.z + u1.z + bb.z, 0.f);                            \
            va1.w = fmaxf(va1.w + u1.w + bb.w, 0.f);                            \
        }                                                                       \
        const float* wp = Wt + (size_t)(kg + wkk) * ldw + colBase + wc4;        \
        vw0 = *(const float4*)wp;                                               \
        vw1 = *(const float4*)(wp + 8  * (size_t)ldw);                          \
        vw2 = *(const float4*)(wp + 16 * (size_t)ldw);                          \
        vw3 = *(const float4*)(wp + 24 * (size_t)ldw);                          \
    }

#define STORE_T(bi)                                                             \
    {                                                                           \
        float* as = As + (bi) * SA_BUF;                                         \
        float* ws = Ws + (bi) * SW_BUF;                                         \
        as[(akq * 4 + 0) * ASP + arow]      = va0.x;                            \
        as[(akq * 4 + 1) * ASP + arow]      = va0.y;                            \
        as[(akq * 4 + 2) * ASP + arow]      = va0.z;                            \
        as[(akq * 4 + 3) * ASP + arow]      = va0.w;                            \
        as[(akq * 4 + 0) * ASP + arow + 16] = va1.x;                            \
        as[(akq * 4 + 1) * ASP + arow + 16] = va1.y;                            \
        as[(akq * 4 + 2) * ASP + arow + 16] = va1.z;                            \
        as[(akq * 4 + 3) * ASP + arow + 16] = va1.w;                            \
        *(float4*)(ws + (wkk + 0)  * WSP + wc4) = vw0;                          \
        *(float4*)(ws + (wkk + 8)  * WSP + wc4) = vw1;                          \
        *(float4*)(ws + (wkk + 16) * WSP + wc4) = vw2;                          \
        *(float4*)(ws + (wkk + 24) * WSP + wc4) = vw3;                          \
    }

    LOAD_T(0);
    STORE_T(0);
    __syncthreads();

    for (int kt = 0; kt < nkt; kt++) {
        if (kt + 1 < nkt) LOAD_T(kt + 1);
        {
            const float* as = As + (kt & 1) * SA_BUF;
            const float* ws = Ws + (kt & 1) * SW_BUF;
#pragma unroll
            for (int kk = 0; kk < 32; kk++) {
                ull a01 = *(const ull*)(as + kk * ASP + ty2);
                float a0, a1;
                unpack2(a01, a0, a1);
                ull d0 = pack2(a0, a0);
                ull d1 = pack2(a1, a1);
                ulonglong2 wA = *(const ulonglong2*)(ws + kk * WSP + tx4);
                ulonglong2 wB = *(const ulonglong2*)(ws + kk * WSP + 32 + tx4);
                fma2(c00, d0, wA.x);
                fma2(c01, d0, wA.y);
                fma2(c02, d0, wB.x);
                fma2(c03, d0, wB.y);
                fma2(c10, d1, wA.x);
                fma2(c11, d1, wA.y);
                fma2(c12, d1, wB.x);
                fma2(c13, d1, wB.y);
            }
        }
        if (kt + 1 < nkt) STORE_T((kt + 1) & 1);
        __syncthreads();
    }
#undef LOAD_T
#undef STORE_T

    // epilogue: rows rowBase+ty2, +1; col blocks at tx4 and 32+tx4
    float4 o00, o01, o10, o11;
    unpack2(c00, o00.x, o00.y); unpack2(c01, o00.z, o00.w);
    unpack2(c02, o01.x, o01.y); unpack2(c03, o01.z, o01.w);
    unpack2(c10, o10.x, o10.y); unpack2(c11, o10.z, o10.w);
    unpack2(c12, o11.x, o11.y); unpack2(c13, o11.z, o11.w);
    if (EPI != EPI_RAW) {
        float4 b0 = *(const float4*)(bias + colBase + tx4);
        float4 b1 = *(const float4*)(bias + colBase + 32 + tx4);
        o00.x += b0.x; o00.y += b0.y; o00.z += b0.z; o00.w += b0.w;
        o10.x += b0.x; o10.y += b0.y; o10.z += b0.z; o10.w += b0.w;
        o01.x += b1.x; o01.y += b1.y; o01.z += b1.z; o01.w += b1.w;
        o11.x += b1.x; o11.y += b1.y; o11.z += b1.z; o11.w += b1.w;
        if (EPI == EPI_TANH) {
            o00.x = tanhf(o00.x); o00.y = tanhf(o00.y); o00.z = tanhf(o00.z); o00.w = tanhf(o00.w);
            o01.x = tanhf(o01.x); o01.y = tanhf(o01.y); o01.z = tanhf(o01.z); o01.w = tanhf(o01.w);
            o10.x = tanhf(o10.x); o10.y = tanhf(o10.y); o10.z = tanhf(o10.z); o10.w = tanhf(o10.w);
            o11.x = tanhf(o11.x); o11.y = tanhf(o11.y); o11.z = tanhf(o11.z); o11.w = tanhf(o11.w);
        }
    }
    float* crow0 = C + (size_t)(rowBase + ty2) * ldc + colBase;
    float* crow1 = crow0 + ldc;
    *(float4*)(crow0 + tx4)      = o00;
    *(float4*)(crow0 + 32 + tx4) = o01;
    *(float4*)(crow1 + tx4)      = o10;
    *(float4*)(crow1 + 32 + tx4) = o11;
}

struct P {
    const float *b1, *b2, *b3, *bih, *bhh;
};

__device__ __forceinline__ void do_g(int gq, bool is_gi, const P& p,
                                     float* As, float* Ws)
{
    int rt = gq / 12, ct = gq % 12;
    if (is_gi)
        gemm32x64<EPI_BIAS, false>(&g_c[0][0], 0, 0, HH, 0, g_WihT, H3, p.bih,
                                   &g_gi[0][0], H3, rt * 32, ct * 64, 8, As, Ws);
    else
        gemm32x64<EPI_BIAS, false>(&g_h[0][0], 0, 0, HH, 0, g_WhhT, H3, p.bhh,
                                   &g_gh[0][0], H3, rt * 32, ct * 64, 8, As, Ws);
}

// phases 0..2: 192 jobs (128 a-layer + 64 g); phase 3: 192 g jobs (epilogue)
__device__ void phase_jobs(int ph, int bid, const P& p, float* As, float* Ws)
{
    if (bid >= 192) return;
    int j = bid;
    if (ph < 3 && j < 128) {
        int rt = j >> 4, kh = (j >> 3) & 1, ct = j & 7;
        int rb = rt * 32, cb = ct * 64, ko = kh * 256;
        if (ph == 0)
            gemm32x64<EPI_RAW, false>(&g_com[0][0], 0, 0, H2, ko, g_W1t, H2, 0,
                                      &g_a1p[kh][0][0], H2, rb, cb, 8, As, Ws);
        else if (ph == 1)
            gemm32x64<EPI_RAW, true>(&g_a1p[0][0][0], &g_a1p[1][0][0], p.b1, H2, ko,
                                     g_W2t, H2, 0, &g_a2p[kh][0][0], H2, rb, cb, 8, As, Ws);
        else
            gemm32x64<EPI_RAW, true>(&g_a2p[0][0][0], &g_a2p[1][0][0], p.b2, H2, ko,
                                     g_W3t, H2, 0, &g_a3p[kh][0][0], H2, rb, cb, 8, As, Ws);
    } else if (ph == 3) {
        if (j < 96) do_g(j, true, p, As, Ws);
        else        do_g(j - 96, false, p, As, Ws);
    } else if (ph == 0) {
        do_g(j - 128, true, p, As, Ws);                        // gi 0..63
    } else if (ph == 1) {
        if (j < 160) do_g(64 + (j - 128), true, p, As, Ws);    // gi 64..95
        else         do_g(j - 160, false, p, As, Ws);          // gh 0..31
    } else {
        do_g(32 + (j - 128), false, p, As, Ws);                // gh 32..95
    }
}

// =========================== persistent megakernel ===========================
__global__ void __launch_bounds__(NTHR)
rnn_persistent(const float* __restrict__ input, const float* __restrict__ noise,
               const float* __restrict__ Wcin, const float* __restrict__ bcin,
               const float* __restrict__ W1, const float* __restrict__ b1,
               const float* __restrict__ W2, const float* __restrict__ b2,
               const float* __restrict__ W3, const float* __restrict__ b3,
               const float* __restrict__ W4, const float* __restrict__ b4,
               const float* __restrict__ Wih, const float* __restrict__ Whh,
               const float* __restrict__ bih, const float* __restrict__ bhh,
               float* __restrict__ outC, float* __restrict__ outH,
               float* __restrict__ outF)
{
    __shared__ __align__(16) float sAs[2 * SA_BUF];
    __shared__ __align__(16) float sWs[2 * SW_BUF];
    __shared__ float su[8];

    const int bid = blockIdx.x;
    const int tid = threadIdx.x;
    const int gt  = bid * NTHR + tid;

    P p { b1, b2, b3, bih, bhh };

    // -------- weight transposes (once) --------
    for (int i = gt; i < H2 * H2; i += GSTRIDE) {
        int k = i / H2, n = i % H2;
        g_W1t[i] = W1[(size_t)n * H2 + k];
        g_W2t[i] = W2[(size_t)n * H2 + k];
        g_W3t[i] = W3[(size_t)n * H2 + k];
    }
    for (int i = gt; i < HH * H3; i += GSTRIDE) {
        int k = i / H3, n = i % H3;
        g_WihT[i] = Wih[(size_t)n * HH + k];
        g_WhhT[i] = Whh[(size_t)n * HH + k];
    }
    for (int i = gt; i < II * HH; i += GSTRIDE) {
        int k = i / HH, n = i % HH;
        g_WcinT[i] = Wcin[(size_t)n * II + k];
    }
    grid_sync();

    // -------- prologue: c_in = tanh(x @ Wcin^T) -> c_concat (row = b*T+t) --------
    for (int j = bid; j < 16384; j += GRID) {
        int rt = j >> 2, ct = j & 3;
        gemm32x64<EPI_TANH, false>(input, 0, 0, II, 0, g_WcinT, HH, bcin,
                                   outC, HH, rt * 32, ct * 64, 4, sAs, sWs);
    }
    grid_sync();

    // -------- init state --------
    if (bid < BB) {
        int b = bid;
        for (int j = tid; j < HH; j += NTHR) {
            g_c[b][j] = 0.f;
            g_h[b][j] = 0.f;
            g_com[b][j] = 0.f;
            g_com[b][HH + j] = outC[(size_t)b * TT * HH + j];
        }
        if (tid == 0) g_n[b] = 0.f;
    }
    grid_sync();

    // -------- recurrent loop --------
    for (int t = 0; t < TT; t++) {
        phase_jobs(0, bid, p, sAs, sWs);   // a1 partials + gi[0:64)
        grid_sync();
        phase_jobs(1, bid, p, sAs, sWs);   // a2 + gi[64:96) + gh[0:32)
        grid_sync();
        phase_jobs(2, bid, p, sAs, sWs);   // a3 + gh[32:96)
        grid_sync();

        // -------- phase U --------
        if (bid < BB) {
            int b = bid;
            float part = 0.f;
#pragma unroll
            for (int q = 0; q < 4; q++) {
                int k = tid + q * NTHR;
                float v = g_a3p[0][b][k] + g_a3p[1][b][k] + b3[k];
                part += fmaxf(v, 0.f) * W4[k];
            }
#pragma unroll
            for (int sh = 16; sh > 0; sh >>= 1)
                part += __shfl_down_sync(0xffffffffu, part, sh);
            if ((tid & 31) == 0) su[tid >> 5] = part;
            __syncthreads();
            if (tid == 0) {
                float logit = b4[0] + su[0] + su[1] + su[2] + su[3];
                float u = noise[(size_t)t * BB + b];
                float logistic = logf(u) - log1pf(-u);
                float a = sigf((logit + logistic) * 10.f);   // / TEMP
                float nold = g_n[b];
                su[4] = a;
                su[5] = nold;
                g_n[b] = nold * (1.f - a) + 1.f;
            }
            __syncthreads();
            float alpha = su[4], nold = su[5];
            float nnew = nold * (1.f - alpha) + 1.f;
#pragma unroll
            for (int u2 = 0; u2 < 2; u2++) {
                int jj = tid + u2 * NTHR;
                float c = g_c[b][jj], h = g_h[b][jj];
                float cin = outC[(size_t)b * TT * HH + (size_t)t * HH + jj];
                float r  = sigf(g_gi[b][jj] + g_gh[b][jj]);
                float z  = sigf(g_gi[b][HH + jj] + g_gh[b][HH + jj]);
                float ng = tanhf(g_gi[b][2 * HH + jj] + r * g_gh[b][2 * HH + jj]);
                float hcand = (1.f - z) * ng + z * h;
                float hnew = h * (1.f - alpha) + alpha * hcand;
                float cnew = (c * nold * (1.f - alpha) + cin) / nnew;
                g_c[b][jj] = cnew;
                g_h[b][jj] = hnew;
                outH[(size_t)b * TT * HH + (size_t)t * HH + jj] = hnew;
                g_com[b][jj] = cnew;
                if (t + 1 < TT)
                    g_com[b][HH + jj] = outC[(size_t)b * TT * HH + (size_t)(t + 1) * HH + jj];
            }
        }
        grid_sync();
    }

    // -------- epilogue: h_final = gru_cell(c_T, h_T) --------
    phase_jobs(3, bid, p, sAs, sWs);
    grid_sync();
    if (bid < BB) {
        int b = bid;
#pragma unroll
        for (int u2 = 0; u2 < 2; u2++) {
            int jj = tid + u2 * NTHR;
            float h = g_h[b][jj];
            float r  = sigf(g_gi[b][jj] + g_gh[b][jj]);
            float z  = sigf(g_gi[b][HH + jj] + g_gh[b][HH + jj]);
            float ng = tanhf(g_gi[b][2 * HH + jj] + r * g_gh[b][2 * HH + jj]);
            outF[(size_t)b * HH + jj] = (1.f - z) * ng + z * h;
        }
    }
}

extern "C" void kernel_launch(void* const* d_in, const int* in_sizes, int n_in,
                              void* d_out, int out_size)
{
    const float* input = (const float*)d_in[0];
    const float* noise = (const float*)d_in[1];
    const float* Wcin  = (const float*)d_in[2];
    const float* bcin  = (const float*)d_in[3];
    const float* W1    = (const float*)d_in[4];
    const float* b1    = (const float*)d_in[5];
    const float* W2    = (const float*)d_in[6];
    const float* b2    = (const float*)d_in[7];
    const float* W3    = (const float*)d_in[8];
    const float* b3    = (const float*)d_in[9];
    const float* W4    = (const float*)d_in[10];
    const float* b4    = (const float*)d_in[11];
    const float* Wih   = (const float*)d_in[12];
    const float* Whh   = (const float*)d_in[13];
    const float* bih   = (const float*)d_in[14];
    const float* bhh   = (const float*)d_in[15];

    float* outC = (float*)d_out;                   // c_concat [B,T,H]
    float* outH = outC + (size_t)BB * TT * HH;     // h_concat [B,T,H]
    float* outF = outH + (size_t)BB * TT * HH;     // h_final  [B,H]

    rnn_persistent<<<GRID, NTHR>>>(input, noise, Wcin, bcin, W1, b1, W2, b2,
                                   W3, b3, W4, b4, Wih, Whh, bih, bhh,
                                   outC, outH, outF);
}